// round 8
// baseline (speedup 1.0000x reference)
#include <cuda_runtime.h>
#include <cstdint>

#define HW 16384
#define OFF_PI 0
#define OFF_MU 2097152
#define OFF_SIG 35651584
#define OFF_G 37748736

// shared layout (float offsets). SH_W is reused as the mu_new tile after the
// GEMM completes (weights dead by then).
#define SH_W 0         // 152*128 = 19456 : Wmu^T [c][o]  /  mu_new [o][pix]
#define SH_S 19456     // 152*8   : Wsig^T [c][j]
#define SH_X 20672     // 16*128  : x tile [c][pix]
#define SH_R 22720     // 8*128   : rho   [k][pix]
#define SH_AL 23744    // 8*128   : alpha [k][pix]
#define SH_PIV 24768   // 8*128   : pi    [k][pix]
#define SH_BMU 25792   // 128
#define SH_WPI 25920   // 128
#define SH_MISC 26048  // 32 : bpi[0..7] bsig[8..15] Wg[16..23] bg[24]
#define SH_MU 26080    // 2 x 8*128 : double-buffered mu group tile
#define SH_TOT 28128
#define SMEM_BYTES (SH_TOT * 4)

typedef unsigned long long ull;

__device__ __forceinline__ ull pack2(float a, float b) {
    ull r;
    asm("mov.b64 %0, {%1,%2};" : "=l"(r) : "f"(a), "f"(b));
    return r;
}
__device__ __forceinline__ ull ffma2(ull a, ull b, ull c) {
    ull d;
    asm("fma.rn.f32x2 %0, %1, %2, %3;" : "=l"(d) : "l"(a), "l"(b), "l"(c));
    return d;
}
__device__ __forceinline__ float2 unpack2(ull v) {
    float2 f;
    asm("mov.b64 {%0,%1}, %2;" : "=f"(f.x), "=f"(f.y) : "l"(v));
    return f;
}

// one K-channel step for 16 outputs x 4 pixels:
// 4 broadcast LDS.128 (16 weights) + 32 ffma2
__device__ __forceinline__ void gemm_step16(ull acc[4][8], const float* wp,
                                            float4 v) {
    ulonglong2 W0 = reinterpret_cast<const ulonglong2*>(wp)[0];
    ulonglong2 W1 = reinterpret_cast<const ulonglong2*>(wp)[1];
    ulonglong2 W2 = reinterpret_cast<const ulonglong2*>(wp)[2];
    ulonglong2 W3 = reinterpret_cast<const ulonglong2*>(wp)[3];
    ull wv[8] = {W0.x, W0.y, W1.x, W1.y, W2.x, W2.y, W3.x, W3.y};
    ull vv[4] = {pack2(v.x, v.x), pack2(v.y, v.y), pack2(v.z, v.z),
                 pack2(v.w, v.w)};
#pragma unroll
    for (int q = 0; q < 8; q++) {
#pragma unroll
        for (int p = 0; p < 4; p++) acc[p][q] = ffma2(vv[p], wv[q], acc[p][q]);
    }
}

extern "C" __global__ void __launch_bounds__(256, 2)
gmm_block_kernel(const float* __restrict__ x, const float* __restrict__ pi_in,
                 const float* __restrict__ mu, const float* __restrict__ sigma,
                 const float* __restrict__ Wpi, const float* __restrict__ bpi,
                 const float* __restrict__ Wmu, const float* __restrict__ bmu,
                 const float* __restrict__ Wsig, const float* __restrict__ bsig,
                 const float* __restrict__ Wg, const float* __restrict__ bg,
                 float* __restrict__ out) {
    extern __shared__ float sh[];
    const int tid = threadIdx.x;
    const int w = tid >> 5;      // warp = component (16 outputs), 0..7
    const int l = tid & 31;      // lane = pixel quad (pixels 4l..4l+3)
    const int blk = blockIdx.x;  // 2048 CTAs x 128 pixels
    const int b = blk >> 7;
    const int hw0 = (blk & 127) << 7;

    // ---- mu group prefetch plumbing (8 channels x 128 pixels per group) ---
    // one 16B cp.async per thread per group
    const int mrow = tid >> 5;          // 0..7 channel-in-group
    const int mcol = (tid & 31) * 4;    // float offset in row
    const float* musrc =
        mu + (b * 128 + mrow) * HW + hw0 + mcol;
    uint32_t mdst[2];
    mdst[0] = (uint32_t)__cvta_generic_to_shared(sh + SH_MU + mrow * 128 + mcol);
    mdst[1] = mdst[0] + 4096;  // second buffer, 1024 floats later

#define ISSUE_GROUP(g)                                                        \
    do {                                                                      \
        asm volatile("cp.async.cg.shared.global [%0], [%1], 16;" ::"r"(       \
                         mdst[(g)&1]),                                        \
                     "l"(musrc + (g) * 8 * HW)                                \
                     : "memory");                                             \
        asm volatile("cp.async.commit_group;" ::: "memory");                  \
    } while (0)

    ISSUE_GROUP(0);
    ISSUE_GROUP(1);

    // ---------------- stage 1: stage weights + x tile ----------------------
    for (int i = tid; i < 19456; i += 256) {  // Wmu[o][c] -> shW[c][o]
        int o = i / 152, c = i - o * 152;
        sh[SH_W + c * 128 + o] = Wmu[i];
    }
    for (int i = tid; i < 1216; i += 256) {  // Wsig[j][c] -> shS[c][j]
        int j = i / 152, c = i - j * 152;
        sh[SH_S + c * 8 + j] = Wsig[i];
    }
    for (int i = tid; i < 2048; i += 256) {
        int c = i >> 7, p = i & 127;
        sh[SH_X + i] = x[(b * 16 + c) * HW + hw0 + p];
    }
    if (tid < 128) {
        sh[SH_BMU + tid] = bmu[tid];
        sh[SH_WPI + tid] = Wpi[tid];
    } else if (tid < 136) {
        int k = tid - 128;
        sh[SH_MISC + k] = bpi[k];
        sh[SH_MISC + 8 + k] = bsig[k];
        sh[SH_MISC + 16 + k] = Wg[k];
    }
    if (tid == 255) sh[SH_MISC + 24] = bg[0];
    __syncthreads();

    const int obase = w * 16;

    ull acc[4][8];
#pragma unroll
    for (int q = 0; q < 8; q++) {
        ull bb = *reinterpret_cast<const ull*>(sh + SH_BMU + obase + 2 * q);
#pragma unroll
        for (int p = 0; p < 4; p++) acc[p][q] = bb;
    }

    // ---------------- phase A: x channels 0..15 ----------------------------
#pragma unroll 4
    for (int c = 0; c < 16; c++) {
        float4 xv =
            *reinterpret_cast<const float4*>(sh + SH_X + c * 128 + 4 * l);
        gemm_step16(acc, sh + SH_W + c * 128 + obase, xv);
    }

    // ---------------- phase B: 16 pipelined mu groups of 8 channels --------
    float4 dk = make_float4(0.f, 0.f, 0.f, 0.f);
    float4 sg4, pv4;
#pragma unroll 1
    for (int g = 0; g < 16; g++) {
        if (g == 15)
            asm volatile("cp.async.wait_group 0;" ::: "memory");
        else
            asm volatile("cp.async.wait_group 1;" ::: "memory");
        __syncthreads();
        const float* mbuf = sh + SH_MU + (g & 1) * 1024;
        const float* wgrp = sh + SH_W + (16 + 8 * g) * 128 + obase;
        if ((g >> 1) == w) {
            if ((g & 1) == 0) {
                // prefetch this component's sigma/pi one group early
                sg4 = *reinterpret_cast<const float4*>(
                    sigma + (b * 8 + w) * HW + hw0 + 4 * l);
                pv4 = *reinterpret_cast<const float4*>(
                    pi_in + (b * 8 + w) * HW + hw0 + 4 * l);
            }
            const int xc0 = (g & 1) * 8;
#pragma unroll
            for (int c = 0; c < 8; c++) {
                float4 mv =
                    *reinterpret_cast<const float4*>(mbuf + c * 128 + 4 * l);
                float4 xv = *reinterpret_cast<const float4*>(
                    sh + SH_X + (xc0 + c) * 128 + 4 * l);
                float d0 = xv.x - mv.x, d1 = xv.y - mv.y;
                float d2 = xv.z - mv.z, d3 = xv.w - mv.w;
                dk.x = fmaf(d0, d0, dk.x);
                dk.y = fmaf(d1, d1, dk.y);
                dk.z = fmaf(d2, d2, dk.z);
                dk.w = fmaf(d3, d3, dk.w);
                gemm_step16(acc, wgrp + c * 128, mv);
            }
            if (g & 1) {
                float4 al4, rho4;
                {
                    float s2 = sg4.x * sg4.x;
                    float t = 6.283185307179586f * s2;
                    float t2 = t * t, t4 = t2 * t2;
                    float dens = __expf(-dk.x / (2.f * s2)) / (t4 * t4);
                    al4.x = pv4.x * dens;
                    rho4.x = al4.x * dens;
                }
                {
                    float s2 = sg4.y * sg4.y;
                    float t = 6.283185307179586f * s2;
                    float t2 = t * t, t4 = t2 * t2;
                    float dens = __expf(-dk.y / (2.f * s2)) / (t4 * t4);
                    al4.y = pv4.y * dens;
                    rho4.y = al4.y * dens;
                }
                {
                    float s2 = sg4.z * sg4.z;
                    float t = 6.283185307179586f * s2;
                    float t2 = t * t, t4 = t2 * t2;
                    float dens = __expf(-dk.z / (2.f * s2)) / (t4 * t4);
                    al4.z = pv4.z * dens;
                    rho4.z = al4.z * dens;
                }
                {
                    float s2 = sg4.w * sg4.w;
                    float t = 6.283185307179586f * s2;
                    float t2 = t * t, t4 = t2 * t2;
                    float dens = __expf(-dk.w / (2.f * s2)) / (t4 * t4);
                    al4.w = pv4.w * dens;
                    rho4.w = al4.w * dens;
                }
                *reinterpret_cast<float4*>(sh + SH_AL + w * 128 + 4 * l) = al4;
                *reinterpret_cast<float4*>(sh + SH_PIV + w * 128 + 4 * l) = pv4;
                *reinterpret_cast<float4*>(sh + SH_R + w * 128 + 4 * l) = rho4;
            }
        } else {
#pragma unroll
            for (int c = 0; c < 8; c++) {
                float4 mv =
                    *reinterpret_cast<const float4*>(mbuf + c * 128 + 4 * l);
                gemm_step16(acc, wgrp + c * 128, mv);
            }
        }
        __syncthreads();  // all reads of buffer (g&1) done
        if (g + 2 < 16) ISSUE_GROUP(g + 2);
    }

    // ---------------- phase C: rho channels 144..151 -----------------------
#pragma unroll 4
    for (int r = 0; r < 8; r++) {
        float4 rv =
            *reinterpret_cast<const float4*>(sh + SH_R + r * 128 + 4 * l);
        gemm_step16(acc, sh + SH_W + (144 + r) * 128 + obase, rv);
    }
    __syncthreads();  // all weight reads done; SH_W becomes the mu_new tile

    // ---------------- epilogue: relu, store mu_new (gmem + smem tile) ------
    {
        float* outMu = out + OFF_MU + (b * 128 + obase) * HW + hw0 + 4 * l;
#pragma unroll
        for (int q = 0; q < 8; q++) {
            float2 f0 = unpack2(acc[0][q]);
            float2 f1 = unpack2(acc[1][q]);
            float2 f2 = unpack2(acc[2][q]);
            float2 f3 = unpack2(acc[3][q]);
            float4 lo = make_float4(fmaxf(f0.x, 0.f), fmaxf(f1.x, 0.f),
                                    fmaxf(f2.x, 0.f), fmaxf(f3.x, 0.f));
            float4 hi = make_float4(fmaxf(f0.y, 0.f), fmaxf(f1.y, 0.f),
                                    fmaxf(f2.y, 0.f), fmaxf(f3.y, 0.f));
            *reinterpret_cast<float4*>(outMu + (2 * q) * HW) = lo;
            *reinterpret_cast<float4*>(outMu + (2 * q + 1) * HW) = hi;
            *reinterpret_cast<float4*>(sh + SH_W + (obase + 2 * q) * 128 +
                                       4 * l) = lo;
            *reinterpret_cast<float4*>(sh + SH_W + (obase + 2 * q + 1) * 128 +
                                       4 * l) = hi;
        }
    }
    __syncthreads();

    // ---------------- finalize (128 threads, one pixel each) ---------------
    if (tid < 128) {
        const int p = tid;
        float piv[8], al[8], z[8], pin[8];
#pragma unroll
        for (int k = 0; k < 8; k++) {
            piv[k] = sh[SH_PIV + k * 128 + p];
            al[k] = sh[SH_AL + k * 128 + p];
        }
        float zmax = -1e30f;
#pragma unroll
        for (int j = 0; j < 8; j++) {
            float zj = sh[SH_MISC + j];
#pragma unroll
            for (int i = 0; i < 8; i++) {
                zj = fmaf(sh[SH_WPI + j * 16 + i], piv[i], zj);
                zj = fmaf(sh[SH_WPI + j * 16 + 8 + i], al[i], zj);
            }
            z[j] = zj;
            zmax = fmaxf(zmax, zj);
        }
        float s = 0.f;
#pragma unroll
        for (int j = 0; j < 8; j++) {
            z[j] = __expf(z[j] - zmax);
            s += z[j];
        }
        float inv = 1.0f / s;
#pragma unroll
        for (int j = 0; j < 8; j++) {
            pin[j] = z[j] * inv;
            out[OFF_PI + (b * 8 + j) * HW + hw0 + p] = pin[j];
        }

        float sj[8];
#pragma unroll
        for (int j = 0; j < 8; j++) sj[j] = sh[SH_MISC + 8 + j];
#pragma unroll 4
        for (int c = 0; c < 16; c++) {
            float xv = sh[SH_X + c * 128 + p];
#pragma unroll
            for (int j = 0; j < 8; j++)
                sj[j] = fmaf(sh[SH_S + c * 8 + j], xv, sj[j]);
        }
        float d2[8];
#pragma unroll 1
        for (int k = 0; k < 8; k++) {
            float dkk = 0.f;
#pragma unroll
            for (int c2 = 0; c2 < 16; c2++) {
                int c = k * 16 + c2;
                float mn = sh[SH_W + c * 128 + p];  // mu_new tile
#pragma unroll
                for (int j = 0; j < 8; j++)
                    sj[j] = fmaf(sh[SH_S + (16 + c) * 8 + j], mn, sj[j]);
                float d = sh[SH_X + c2 * 128 + p] - mn;
                dkk = fmaf(d, d, dkk);
            }
            d2[k] = dkk;
        }
#pragma unroll
        for (int r = 0; r < 8; r++) {
            float rv = sh[SH_R + r * 128 + p];
#pragma unroll
            for (int j = 0; j < 8; j++)
                sj[j] = fmaf(sh[SH_S + (144 + r) * 8 + j], rv, sj[j]);
        }

        float g = sh[SH_MISC + 24];
#pragma unroll
        for (int j = 0; j < 8; j++) {
            float sn = __expf(fmaxf(sj[j], 0.f));
            out[OFF_SIG + (b * 8 + j) * HW + hw0 + p] = sn;
            float s2 = sn * sn;
            float t = 6.283185307179586f * s2;
            float t2 = t * t, t4 = t2 * t2;
            float dens2 = __expf(-d2[j] / (2.f * s2)) / (t4 * t4);
            g = fmaf(sh[SH_MISC + 16 + j], pin[j] * dens2, g);
        }
        out[OFF_G + b * HW + hw0 + p] = 1.0f / (1.0f + __expf(-g));
    }
}

extern "C" void kernel_launch(void* const* d_in, const int* in_sizes, int n_in,
                              void* d_out, int out_size) {
    (void)in_sizes;
    (void)n_in;
    (void)out_size;
    const float* x = (const float*)d_in[0];
    const float* pi = (const float*)d_in[1];
    const float* mu = (const float*)d_in[2];
    const float* sigma = (const float*)d_in[3];
    const float* Wpi = (const float*)d_in[4];
    const float* bpi = (const float*)d_in[5];
    const float* Wmu = (const float*)d_in[6];
    const float* bmu = (const float*)d_in[7];
    const float* Wsig = (const float*)d_in[8];
    const float* bsig = (const float*)d_in[9];
    const float* Wg = (const float*)d_in[10];
    const float* bg = (const float*)d_in[11];
    float* out = (float*)d_out;

    cudaFuncSetAttribute(gmm_block_kernel,
                         cudaFuncAttributeMaxDynamicSharedMemorySize,
                         SMEM_BYTES);
    gmm_block_kernel<<<2048, 256, SMEM_BYTES>>>(x, pi, mu, sigma, Wpi, bpi, Wmu,
                                                bmu, Wsig, bsig, Wg, bg, out);
}

// round 11
// speedup vs baseline: 1.5009x; 1.5009x over previous
#include <cuda_runtime.h>
#include <cuda_bf16.h>
#include <cstdint>

#define HW 16384
#define OFF_PI 0
#define OFF_MU 2097152
#define OFF_SIG 35651584
#define OFF_G 37748736

#define KPAD 168  // padded K stride (channels); 152 real + zeros

// smem byte offsets
#define SMB_AH 0        // A hi bf16 [128 px][KPAD]  -> later mn tile (fp32)
#define SMB_AL 43008    // A lo bf16
#define SMB_BH 86016    // B hi bf16 [128 out][KPAD]
#define SMB_BL 129024   // B lo bf16
#define SMB_X 172032    // x fp32 [16][128]
#define SMB_R 180224    // rho fp32 [8][128]
#define SMB_ALF 184320  // alpha [8][128]
#define SMB_PIV 188416  // pi [8][128]
#define SMB_S 192512    // Wsig^T fp32 [152][8]
#define SMB_BMU 197376  // 128 f
#define SMB_WPI 197888  // 128 f
#define SMB_MISC 198400 // bpi[0..7] bsig[8..15] Wg[16..23] bg[24]
#define SMEM_BYTES 198528

// mn tile (fp32 mu_new pre-bias, [out][132]) reuses SMB_AH region (67.6KB)
#define MN_STRIDE 132

typedef unsigned long long ull;

// Precomputed Wmu bf16 hi/lo tiles, [128][KPAD] row-major, contiguous.
__device__ __align__(16) __nv_bfloat16 g_B[2][128 * KPAD];

extern "C" __global__ void prep_B_kernel(const float* __restrict__ Wmu) {
    int i = blockIdx.x * 256 + threadIdx.x;
    if (i >= 128 * KPAD) return;
    int o = i / KPAD, c = i - o * KPAD;
    float v = (c < 152) ? Wmu[o * 152 + c] : 0.f;
    __nv_bfloat16 hi = __float2bfloat16(v);
    __nv_bfloat16 lo = __float2bfloat16(v - __bfloat162float(hi));
    g_B[0][i] = hi;
    g_B[1][i] = lo;
}

__device__ __forceinline__ void hmma_bf16(float* d, uint32_t a0, uint32_t a1,
                                          uint32_t a2, uint32_t a3,
                                          uint32_t b0, uint32_t b1) {
    asm volatile(
        "mma.sync.aligned.m16n8k16.row.col.f32.bf16.bf16.f32 "
        "{%0,%1,%2,%3}, {%4,%5,%6,%7}, {%8,%9}, {%0,%1,%2,%3};"
        : "+f"(d[0]), "+f"(d[1]), "+f"(d[2]), "+f"(d[3])
        : "r"(a0), "r"(a1), "r"(a2), "r"(a3), "r"(b0), "r"(b1));
}

// pack 8 consecutive-channel fp32 -> 4 bf16x2 hi words + 4 lo words
__device__ __forceinline__ void pack8(const float* v, uint4& hi, uint4& lo) {
    uint32_t h[4], l[4];
#pragma unroll
    for (int i = 0; i < 4; i++) {
        float a = v[2 * i], c = v[2 * i + 1];
        __nv_bfloat162 h2 = __floats2bfloat162_rn(a, c);
        float2 hf = __bfloat1622float2(h2);
        __nv_bfloat162 l2 = __floats2bfloat162_rn(a - hf.x, c - hf.y);
        h[i] = *(uint32_t*)&h2;
        l[i] = *(uint32_t*)&l2;
    }
    hi = make_uint4(h[0], h[1], h[2], h[3]);
    lo = make_uint4(l[0], l[1], l[2], l[3]);
}

extern "C" __global__ void __launch_bounds__(256)
gmm_block_kernel(const float* __restrict__ x, const float* __restrict__ pi_in,
                 const float* __restrict__ mu, const float* __restrict__ sigma,
                 const float* __restrict__ Wpi, const float* __restrict__ bpi,
                 const float* __restrict__ Wmu, const float* __restrict__ bmu,
                 const float* __restrict__ Wsig, const float* __restrict__ bsig,
                 const float* __restrict__ Wg, const float* __restrict__ bg,
                 float* __restrict__ out) {
    extern __shared__ char sm[];
    float* shX = (float*)(sm + SMB_X);
    float* shR = (float*)(sm + SMB_R);
    float* shAL = (float*)(sm + SMB_ALF);
    float* shPIV = (float*)(sm + SMB_PIV);
    float* shS = (float*)(sm + SMB_S);
    float* shBMU = (float*)(sm + SMB_BMU);
    float* shWPI = (float*)(sm + SMB_WPI);
    float* shMISC = (float*)(sm + SMB_MISC);
    uint32_t* AH32 = (uint32_t*)(sm + SMB_AH);
    uint32_t* AL32 = (uint32_t*)(sm + SMB_AL);
    uint32_t* BH32 = (uint32_t*)(sm + SMB_BH);
    uint32_t* BL32 = (uint32_t*)(sm + SMB_BL);
    float* mn = (float*)(sm + SMB_AH);  // after GEMM

    const int tid = threadIdx.x;
    const int blk = blockIdx.x;  // 2048 CTAs x 128 pixels
    const int b = blk >> 7;
    const int hw0 = (blk & 127) << 7;

    // ---- stage 1: cp.async B tiles (86KB) + stage small operands ----------
    {
        uint32_t dst = (uint32_t)__cvta_generic_to_shared(sm + SMB_BH);
        const char* src = (const char*)&g_B[0][0];
#pragma unroll 1
        for (int i = tid * 16; i < 2 * 128 * KPAD * 2; i += 256 * 16) {
            asm volatile("cp.async.cg.shared.global [%0], [%1], 16;" ::"r"(
                             dst + i),
                         "l"(src + i)
                         : "memory");
        }
        asm volatile("cp.async.commit_group;" ::: "memory");
    }
    for (int i = tid; i < 1216; i += 256) {  // Wsig[j][c] -> shS[c][j]
        int j = i / 152, c = i - j * 152;
        shS[c * 8 + j] = Wsig[i];
    }
    for (int i = tid; i < 2048; i += 256) {
        int c = i >> 7, p = i & 127;
        shX[i] = x[(b * 16 + c) * HW + hw0 + p];
    }
    if (tid < 128) {
        shBMU[tid] = bmu[tid];
        shWPI[tid] = Wpi[tid];
    } else if (tid < 136) {
        int k = tid - 128;
        shMISC[k] = bpi[k];
        shMISC[8 + k] = bsig[k];
        shMISC[16 + k] = Wg[k];
    }
    if (tid == 255) shMISC[24] = bg[0];
    // CRITICAL: shX (and the other stage-1 smem) is read by stage 2 below,
    // and writer/reader threads differ. The cp.async for B stays in flight
    // across this barrier, preserving the load/compute overlap.
    __syncthreads();

    // ---- stage 2: build A tiles [px][KPAD] bf16 hi/lo, fuse dens/alpha/rho
    {
        const int p = tid & 127, h = tid >> 7;
        char* rowH = sm + SMB_AH + p * (KPAD * 2);
        char* rowL = sm + SMB_AL + p * (KPAD * 2);
        float xv[16];
#pragma unroll
        for (int c = 0; c < 16; c++) xv[c] = shX[c * 128 + p];

        if (h == 0) {
            // x channels 0..15
#pragma unroll
            for (int g = 0; g < 2; g++) {
                uint4 hi, lo;
                pack8(xv + 8 * g, hi, lo);
                *(uint4*)(rowH + 16 * g) = hi;
                *(uint4*)(rowL + 16 * g) = lo;
            }
        } else {
            // zero pad channels 152..167
            *(uint4*)(rowH + 304) = make_uint4(0, 0, 0, 0);
            *(uint4*)(rowH + 320) = make_uint4(0, 0, 0, 0);
            *(uint4*)(rowL + 304) = make_uint4(0, 0, 0, 0);
            *(uint4*)(rowL + 320) = make_uint4(0, 0, 0, 0);
        }

        float rhov[4];
#pragma unroll 1
        for (int kg = 0; kg < 4; kg++) {
            int k = 4 * h + kg;
            const float* mk = mu + (b * 128 + k * 16) * HW + hw0 + p;
            float v[16];
#pragma unroll
            for (int c = 0; c < 16; c++) v[c] = mk[c * HW];
            float dk = 0.f;
#pragma unroll
            for (int c = 0; c < 16; c++) {
                float d = xv[c] - v[c];
                dk = fmaf(d, d, dk);
            }
#pragma unroll
            for (int g = 0; g < 2; g++) {
                uint4 hi, lo;
                pack8(v + 8 * g, hi, lo);
                *(uint4*)(rowH + (16 + k * 16 + 8 * g) * 2) = hi;
                *(uint4*)(rowL + (16 + k * 16 + 8 * g) * 2) = lo;
            }
            float sg = sigma[(b * 8 + k) * HW + hw0 + p];
            float pv = pi_in[(b * 8 + k) * HW + hw0 + p];
            float s2 = sg * sg;
            float t = 6.283185307179586f * s2;
            float t2 = t * t, t4 = t2 * t2;
            float dens = __expf(-dk / (2.f * s2)) / (t4 * t4);
            float a = pv * dens;
            shAL[k * 128 + p] = a;
            shPIV[k * 128 + p] = pv;
            float rho = a * dens;
            shR[k * 128 + p] = rho;
            rhov[kg] = rho;
        }
        // rho channels 144+4h..147+4h
        {
            __nv_bfloat162 a2 = __floats2bfloat162_rn(rhov[0], rhov[1]);
            float2 af = __bfloat1622float2(a2);
            __nv_bfloat162 a2l =
                __floats2bfloat162_rn(rhov[0] - af.x, rhov[1] - af.y);
            __nv_bfloat162 b2 = __floats2bfloat162_rn(rhov[2], rhov[3]);
            float2 bf = __bfloat1622float2(b2);
            __nv_bfloat162 b2l =
                __floats2bfloat162_rn(rhov[2] - bf.x, rhov[3] - bf.y);
            *(uint2*)(rowH + (144 + 4 * h) * 2) =
                make_uint2(*(uint32_t*)&a2, *(uint32_t*)&b2);
            *(uint2*)(rowL + (144 + 4 * h) * 2) =
                make_uint2(*(uint32_t*)&a2l, *(uint32_t*)&b2l);
        }
    }
    asm volatile("cp.async.wait_group 0;" ::: "memory");
    __syncthreads();

    // ---- GEMM: mu_new = A[128px x 160] @ B^T[160 x 128out], bf16 3-pass ---
    // warp w owns pixel rows m0=16w..16w+15, all 128 outputs.
    {
        const int w = tid >> 5, l = tid & 31;
        const int g = l >> 2, t = l & 3;
        const int m0 = 16 * w;

        float acc[16][4];
#pragma unroll
        for (int n = 0; n < 16; n++)
#pragma unroll
            for (int q = 0; q < 4; q++) acc[n][q] = 0.f;

#pragma unroll 1
        for (int k0 = 0; k0 < 160; k0 += 16) {
            // A fragments (hi & lo), canonical m16n8k16 row-major mapping
            const int ar0 = ((m0 + g) * KPAD + k0 + 2 * t) >> 1;
            const int ar1 = ((m0 + g + 8) * KPAD + k0 + 2 * t) >> 1;
            uint32_t ah0 = AH32[ar0], ah1 = AH32[ar1];
            uint32_t ah2 = AH32[ar0 + 4], ah3 = AH32[ar1 + 4];
            uint32_t al0 = AL32[ar0], al1 = AL32[ar1];
            uint32_t al2 = AL32[ar0 + 4], al3 = AL32[ar1 + 4];

            uint32_t bh[16][2];
#pragma unroll
            for (int n = 0; n < 16; n++) {
                const int br = ((8 * n + g) * KPAD + k0 + 2 * t) >> 1;
                bh[n][0] = BH32[br];
                bh[n][1] = BH32[br + 4];
                hmma_bf16(acc[n], ah0, ah1, ah2, ah3, bh[n][0], bh[n][1]);
            }
#pragma unroll
            for (int n = 0; n < 16; n++) {
                const int br = ((8 * n + g) * KPAD + k0 + 2 * t) >> 1;
                uint32_t bl0 = BL32[br], bl1 = BL32[br + 4];
                hmma_bf16(acc[n], ah0, ah1, ah2, ah3, bl0, bl1);
            }
#pragma unroll
            for (int n = 0; n < 16; n++)
                hmma_bf16(acc[n], al0, al1, al2, al3, bh[n][0], bh[n][1]);
        }
        __syncthreads();  // A tiles dead; mn overlays them

        // scatter acc -> mn[out][MN_STRIDE] (pre-bias). Conflict-free banks.
#pragma unroll
        for (int n = 0; n < 16; n++) {
            const int nc = 8 * n + 2 * t;
            mn[nc * MN_STRIDE + m0 + g] = acc[n][0];
            mn[(nc + 1) * MN_STRIDE + m0 + g] = acc[n][1];
            mn[nc * MN_STRIDE + m0 + g + 8] = acc[n][2];
            mn[(nc + 1) * MN_STRIDE + m0 + g + 8] = acc[n][3];
        }
    }
    __syncthreads();

    // ---- finalize (128 threads, one pixel each) ---------------------------
    if (tid < 128) {
        const int p = tid;
        // softmax -> pi_new
        float piv[8], al[8], z[8], pin[8];
#pragma unroll
        for (int k = 0; k < 8; k++) {
            piv[k] = shPIV[k * 128 + p];
            al[k] = shAL[k * 128 + p];
        }
        float zmax = -1e30f;
#pragma unroll
        for (int j = 0; j < 8; j++) {
            float zj = shMISC[j];
#pragma unroll
            for (int i = 0; i < 8; i++) {
                zj = fmaf(shWPI[j * 16 + i], piv[i], zj);
                zj = fmaf(shWPI[j * 16 + 8 + i], al[i], zj);
            }
            z[j] = zj;
            zmax = fmaxf(zmax, zj);
        }
        float s = 0.f;
#pragma unroll
        for (int j = 0; j < 8; j++) {
            z[j] = __expf(z[j] - zmax);
            s += z[j];
        }
        float inv = 1.0f / s;
#pragma unroll
        for (int j = 0; j < 8; j++) {
            pin[j] = z[j] * inv;
            out[OFF_PI + (b * 8 + j) * HW + hw0 + p] = pin[j];
        }

        // mu_new: bias+relu+store; fused sigma matvec + dist2
        float sj[8];
#pragma unroll
        for (int j = 0; j < 8; j++) sj[j] = shMISC[8 + j];
        float d2[8] = {0.f, 0.f, 0.f, 0.f, 0.f, 0.f, 0.f, 0.f};
        float* outMuBase = out + OFF_MU + (b * 128) * HW + hw0 + p;
#pragma unroll 4
        for (int o = 0; o < 128; o++) {
            float v = mn[o * MN_STRIDE + p] + shBMU[o];
            v = fmaxf(v, 0.f);
            outMuBase[o * HW] = v;
            float4 wsa = *(const float4*)(shS + (16 + o) * 8);
            float4 wsb = *(const float4*)(shS + (16 + o) * 8 + 4);
            sj[0] = fmaf(wsa.x, v, sj[0]);
            sj[1] = fmaf(wsa.y, v, sj[1]);
            sj[2] = fmaf(wsa.z, v, sj[2]);
            sj[3] = fmaf(wsa.w, v, sj[3]);
            sj[4] = fmaf(wsb.x, v, sj[4]);
            sj[5] = fmaf(wsb.y, v, sj[5]);
            sj[6] = fmaf(wsb.z, v, sj[6]);
            sj[7] = fmaf(wsb.w, v, sj[7]);
            float d = shX[(o & 15) * 128 + p] - v;
            d2[o >> 4] = fmaf(d, d, d2[o >> 4]);
        }
        // x and rho channels of sigma matvec
#pragma unroll 4
        for (int c = 0; c < 16; c++) {
            float xv = shX[c * 128 + p];
#pragma unroll
            for (int j = 0; j < 8; j++)
                sj[j] = fmaf(shS[c * 8 + j], xv, sj[j]);
        }
#pragma unroll
        for (int r = 0; r < 8; r++) {
            float rv = shR[r * 128 + p];
#pragma unroll
            for (int j = 0; j < 8; j++)
                sj[j] = fmaf(shS[(144 + r) * 8 + j], rv, sj[j]);
        }

        float g = shMISC[24];
#pragma unroll
        for (int j = 0; j < 8; j++) {
            float sn = __expf(fmaxf(sj[j], 0.f));
            out[OFF_SIG + (b * 8 + j) * HW + hw0 + p] = sn;
            float s2 = sn * sn;
            float t = 6.283185307179586f * s2;
            float t2 = t * t, t4 = t2 * t2;
            float dens2 = __expf(-d2[j] / (2.f * s2)) / (t4 * t4);
            g = fmaf(shMISC[16 + j], pin[j] * dens2, g);
        }
        out[OFF_G + b * HW + hw0 + p] = 1.0f / (1.0f + __expf(-g));
    }
}

extern "C" void kernel_launch(void* const* d_in, const int* in_sizes, int n_in,
                              void* d_out, int out_size) {
    (void)in_sizes;
    (void)n_in;
    (void)out_size;
    const float* x = (const float*)d_in[0];
    const float* pi = (const float*)d_in[1];
    const float* mu = (const float*)d_in[2];
    const float* sigma = (const float*)d_in[3];
    const float* Wpi = (const float*)d_in[4];
    const float* bpi = (const float*)d_in[5];
    const float* Wmu = (const float*)d_in[6];
    const float* bmu = (const float*)d_in[7];
    const float* Wsig = (const float*)d_in[8];
    const float* bsig = (const float*)d_in[9];
    const float* Wg = (const float*)d_in[10];
    const float* bg = (const float*)d_in[11];
    float* out = (float*)d_out;

    prep_B_kernel<<<(128 * KPAD + 255) / 256, 256>>>(Wmu);

    cudaFuncSetAttribute(gmm_block_kernel,
                         cudaFuncAttributeMaxDynamicSharedMemorySize,
                         SMEM_BYTES);
    gmm_block_kernel<<<2048, 256, SMEM_BYTES>>>(x, pi, mu, sigma, Wpi, bpi,
                                                Wmu, bmu, Wsig, bsig, Wg, bg,
                                                out);
}

// round 12
// speedup vs baseline: 1.7825x; 1.1876x over previous
#include <cuda_runtime.h>
#include <cuda_bf16.h>
#include <cstdint>

#define HW 16384
#define OFF_PI 0
#define OFF_MU 2097152
#define OFF_SIG 35651584
#define OFF_G 37748736

#define KPAD 168  // B tile K stride (channels); 152 real + zero pad

// smem byte offsets (total 112512 -> 2 CTAs/SM)
#define SMB_B 0         // Bh 43008 | Bl 43008 ; reused as mn tile post-GEMM
#define SMB_SLH 86016   // A-slice hi bf16 [128 px][16 ch] = 4096
#define SMB_SLL 90112   // A-slice lo bf16                 = 4096
#define SMB_X 94208     // x fp32 [16][128]                = 8192
#define SMB_AL 102400   // dist accum -> alpha [8][128]    = 4096
#define SMB_S 106496    // Wsig^T fp32 [152][8]            = 4864
#define SMB_BMU 111360  // 128 f
#define SMB_WPI 111872  // 128 f
#define SMB_MISC 112384 // bpi[0..7] bsig[8..15] Wg[16..23] bg[24]
#define SMEM_BYTES 112512

#define MN_STRIDE 132   // fp32 mu_new tile [128 out][132], lives in SMB_B

typedef unsigned long long ull;

// Precomputed Wmu bf16 hi/lo tiles, [128][KPAD] row-major, contiguous.
__device__ __align__(16) __nv_bfloat16 g_B[2][128 * KPAD];

extern "C" __global__ void prep_B_kernel(const float* __restrict__ Wmu) {
    int i = blockIdx.x * 256 + threadIdx.x;
    if (i >= 128 * KPAD) return;
    int o = i / KPAD, c = i - o * KPAD;
    float v = (c < 152) ? Wmu[o * 152 + c] : 0.f;
    __nv_bfloat16 hi = __float2bfloat16(v);
    __nv_bfloat16 lo = __float2bfloat16(v - __bfloat162float(hi));
    g_B[0][i] = hi;
    g_B[1][i] = lo;
}

__device__ __forceinline__ void hmma_bf16(float* d, uint32_t a0, uint32_t a1,
                                          uint32_t a2, uint32_t a3,
                                          uint32_t b0, uint32_t b1) {
    asm volatile(
        "mma.sync.aligned.m16n8k16.row.col.f32.bf16.bf16.f32 "
        "{%0,%1,%2,%3}, {%4,%5,%6,%7}, {%8,%9}, {%0,%1,%2,%3};"
        : "+f"(d[0]), "+f"(d[1]), "+f"(d[2]), "+f"(d[3])
        : "r"(a0), "r"(a1), "r"(a2), "r"(a3), "r"(b0), "r"(b1));
}

// pack 8 consecutive-channel fp32 -> 4 bf16x2 hi words + 4 lo words
__device__ __forceinline__ void pack8(const float* v, uint4& hi, uint4& lo) {
    uint32_t h[4], l[4];
#pragma unroll
    for (int i = 0; i < 4; i++) {
        float a = v[2 * i], c = v[2 * i + 1];
        __nv_bfloat162 h2 = __floats2bfloat162_rn(a, c);
        float2 hf = __bfloat1622float2(h2);
        __nv_bfloat162 l2 = __floats2bfloat162_rn(a - hf.x, c - hf.y);
        h[i] = *(uint32_t*)&h2;
        l[i] = *(uint32_t*)&l2;
    }
    hi = make_uint4(h[0], h[1], h[2], h[3]);
    lo = make_uint4(l[0], l[1], l[2], l[3]);
}

extern "C" __global__ void __launch_bounds__(256, 2)
gmm_block_kernel(const float* __restrict__ x, const float* __restrict__ pi_in,
                 const float* __restrict__ mu, const float* __restrict__ sigma,
                 const float* __restrict__ Wpi, const float* __restrict__ bpi,
                 const float* __restrict__ Wmu, const float* __restrict__ bmu,
                 const float* __restrict__ Wsig, const float* __restrict__ bsig,
                 const float* __restrict__ Wg, const float* __restrict__ bg,
                 float* __restrict__ out) {
    extern __shared__ char sm[];
    float* shX = (float*)(sm + SMB_X);
    float* shAL = (float*)(sm + SMB_AL);
    float* shS = (float*)(sm + SMB_S);
    float* shBMU = (float*)(sm + SMB_BMU);
    float* shWPI = (float*)(sm + SMB_WPI);
    float* shMISC = (float*)(sm + SMB_MISC);
    uint32_t* SLH32 = (uint32_t*)(sm + SMB_SLH);
    uint32_t* SLL32 = (uint32_t*)(sm + SMB_SLL);
    uint32_t* BH32 = (uint32_t*)(sm + SMB_B);
    uint32_t* BL32 = (uint32_t*)(sm + SMB_B + 43008);
    float* mn = (float*)(sm + SMB_B);  // after GEMM (B dead)

    const int tid = threadIdx.x;
    const int blk = blockIdx.x;  // 2048 CTAs x 128 pixels
    const int b = blk >> 7;
    const int hw0 = (blk & 127) << 7;

    // ---- stage 1: cp.async B (86KB, L2-hot) + stage small operands --------
    {
        uint32_t dst = (uint32_t)__cvta_generic_to_shared(sm + SMB_B);
        const char* src = (const char*)&g_B[0][0];
#pragma unroll 1
        for (int i = tid * 16; i < 86016; i += 256 * 16) {
            asm volatile("cp.async.cg.shared.global [%0], [%1], 16;" ::"r"(
                             dst + i),
                         "l"(src + i)
                         : "memory");
        }
        asm volatile("cp.async.commit_group;" ::: "memory");
    }
    for (int i = tid; i < 1216; i += 256) {  // Wsig[j][c] -> shS[c][j]
        int j = i / 152, c = i - j * 152;
        shS[c * 8 + j] = Wsig[i];
    }
    for (int i = tid; i < 2048; i += 256) {
        int c = i >> 7, p = i & 127;
        shX[i] = x[(b * 16 + c) * HW + hw0 + p];
    }
    if (tid < 128) {
        shBMU[tid] = bmu[tid];
        shWPI[tid] = Wpi[tid];
    } else if (tid < 136) {
        int k = tid - 128;
        shMISC[k] = bpi[k];
        shMISC[8 + k] = bsig[k];
        shMISC[16 + k] = Wg[k];
    }
    if (tid == 255) shMISC[24] = bg[0];
    for (int i = tid; i < 1024; i += 256) shAL[i] = 0.f;  // dist accum
    asm volatile("cp.async.wait_group 0;" ::: "memory");
    __syncthreads();

    // ---- fused slice-streamed GEMM ----------------------------------------
    const int w = tid >> 5, l = tid & 31;
    const int g = l >> 2, t = l & 3;
    const int m0 = 16 * w;
    const int p = tid & 127, h = tid >> 7;  // slice-builder role

    float acc[16][4];
#pragma unroll
    for (int n = 0; n < 16; n++)
#pragma unroll
        for (int q = 0; q < 4; q++) acc[n][q] = 0.f;

#pragma unroll 1
    for (int c = 0; c < 10; c++) {
        // ---- build slice for channels 16c..16c+15 ----
        if (c == 0) {
            // x channels; thread (p,h) owns cols 8h..8h+7
            float v[8];
#pragma unroll
            for (int j = 0; j < 8; j++) v[j] = shX[(8 * h + j) * 128 + p];
            uint4 hi, lo;
            pack8(v, hi, lo);
            *(uint4*)((char*)SLH32 + p * 32 + h * 16) = hi;
            *(uint4*)((char*)SLL32 + p * 32 + h * 16) = lo;
        } else if (c <= 8) {
            const int k = c - 1;
            const float* mk = mu + (b * 128 + k * 16 + 8 * h) * HW + hw0 + p;
            float v[8];
#pragma unroll
            for (int j = 0; j < 8; j++) v[j] = mk[j * HW];
            float dk = 0.f;
#pragma unroll
            for (int j = 0; j < 8; j++) {
                float d = shX[(8 * h + j) * 128 + p] - v[j];
                dk = fmaf(d, d, dk);
            }
            atomicAdd(&shAL[k * 128 + p], dk);  // 2 adds/slot: deterministic
            uint4 hi, lo;
            pack8(v, hi, lo);
            *(uint4*)((char*)SLH32 + p * 32 + h * 16) = hi;
            *(uint4*)((char*)SLL32 + p * 32 + h * 16) = lo;
        } else {
            // c == 9: finalize dens/alpha/rho for all comps, build rho slice
            if (h == 0) {
                float rho[8];
#pragma unroll
                for (int k = 0; k < 8; k++) {
                    float dist = shAL[k * 128 + p];
                    float sg = sigma[(b * 8 + k) * HW + hw0 + p];
                    float pv = pi_in[(b * 8 + k) * HW + hw0 + p];
                    float s2 = sg * sg;
                    float tt = 6.283185307179586f * s2;
                    float t2 = tt * tt, t4 = t2 * t2;
                    float dens = __expf(-dist / (2.f * s2)) / (t4 * t4);
                    float a = pv * dens;
                    shAL[k * 128 + p] = a;  // alpha overwrites dist
                    rho[k] = a * dens;
                }
                uint4 hi, lo;
                pack8(rho, hi, lo);
                *(uint4*)((char*)SLH32 + p * 32) = hi;
                *(uint4*)((char*)SLL32 + p * 32) = lo;
            } else {
                // pad channels 152..159
                *(uint4*)((char*)SLH32 + p * 32 + 16) = make_uint4(0, 0, 0, 0);
                *(uint4*)((char*)SLL32 + p * 32 + 16) = make_uint4(0, 0, 0, 0);
            }
        }
        __syncthreads();

        // ---- consume slice: 48 HMMA (3-pass bf16 split) ----
        const int ar0 = (m0 + g) * 8 + t;
        const int ar1 = (m0 + g + 8) * 8 + t;
        uint32_t ah0 = SLH32[ar0], ah1 = SLH32[ar1];
        uint32_t ah2 = SLH32[ar0 + 4], ah3 = SLH32[ar1 + 4];
        uint32_t al0 = SLL32[ar0], al1 = SLL32[ar1];
        uint32_t al2 = SLL32[ar0 + 4], al3 = SLL32[ar1 + 4];

        uint32_t bh[16][2];
#pragma unroll
        for (int n = 0; n < 16; n++) {
            const int br = (8 * n + g) * 84 + 8 * c + t;
            bh[n][0] = BH32[br];
            bh[n][1] = BH32[br + 4];
            hmma_bf16(acc[n], ah0, ah1, ah2, ah3, bh[n][0], bh[n][1]);
        }
#pragma unroll
        for (int n = 0; n < 16; n++) {
            const int br = (8 * n + g) * 84 + 8 * c + t;
            uint32_t bl0 = BL32[br], bl1 = BL32[br + 4];
            hmma_bf16(acc[n], ah0, ah1, ah2, ah3, bl0, bl1);
        }
#pragma unroll
        for (int n = 0; n < 16; n++)
            hmma_bf16(acc[n], al0, al1, al2, al3, bh[n][0], bh[n][1]);
        __syncthreads();
    }

    // ---- scatter acc -> mn tile (B region dead) ---------------------------
#pragma unroll
    for (int n = 0; n < 16; n++) {
        const int nc = 8 * n + 2 * t;
        mn[nc * MN_STRIDE + m0 + g] = acc[n][0];
        mn[(nc + 1) * MN_STRIDE + m0 + g] = acc[n][1];
        mn[nc * MN_STRIDE + m0 + g + 8] = acc[n][2];
        mn[(nc + 1) * MN_STRIDE + m0 + g + 8] = acc[n][3];
    }
    __syncthreads();

    // ---- finalize (128 threads, one pixel each) ---------------------------
    if (tid < 128) {
        const int pp = tid;
        // rho from chunk-9 slice (hi+lo bf16)
        float rho[8];
        {
            const __nv_bfloat16* rh =
                (const __nv_bfloat16*)((char*)SLH32 + pp * 32);
            const __nv_bfloat16* rl =
                (const __nv_bfloat16*)((char*)SLL32 + pp * 32);
#pragma unroll
            for (int r = 0; r < 8; r++)
                rho[r] = __bfloat162float(rh[r]) + __bfloat162float(rl[r]);
        }
        // softmax -> pi_new (pi re-read from gmem; alpha from shAL)
        float piv[8], al[8], z[8], pin[8];
#pragma unroll
        for (int k = 0; k < 8; k++) {
            piv[k] = pi_in[(b * 8 + k) * HW + hw0 + pp];
            al[k] = shAL[k * 128 + pp];
        }
        float zmax = -1e30f;
#pragma unroll
        for (int j = 0; j < 8; j++) {
            float zj = shMISC[j];
#pragma unroll
            for (int i = 0; i < 8; i++) {
                zj = fmaf(shWPI[j * 16 + i], piv[i], zj);
                zj = fmaf(shWPI[j * 16 + 8 + i], al[i], zj);
            }
            z[j] = zj;
            zmax = fmaxf(zmax, zj);
        }
        float s = 0.f;
#pragma unroll
        for (int j = 0; j < 8; j++) {
            z[j] = __expf(z[j] - zmax);
            s += z[j];
        }
        float inv = 1.0f / s;
#pragma unroll
        for (int j = 0; j < 8; j++) {
            pin[j] = z[j] * inv;
            out[OFF_PI + (b * 8 + j) * HW + hw0 + pp] = pin[j];
        }

        // mu_new: bias+relu+store; fused sigma matvec + dist2
        float sj[8];
#pragma unroll
        for (int j = 0; j < 8; j++) sj[j] = shMISC[8 + j];
        float d2[8] = {0.f, 0.f, 0.f, 0.f, 0.f, 0.f, 0.f, 0.f};
        float* outMuBase = out + OFF_MU + (b * 128) * HW + hw0 + pp;
#pragma unroll 4
        for (int o = 0; o < 128; o++) {
            float v = mn[o * MN_STRIDE + pp] + shBMU[o];
            v = fmaxf(v, 0.f);
            outMuBase[o * HW] = v;
            float4 wsa = *(const float4*)(shS + (16 + o) * 8);
            float4 wsb = *(const float4*)(shS + (16 + o) * 8 + 4);
            sj[0] = fmaf(wsa.x, v, sj[0]);
            sj[1] = fmaf(wsa.y, v, sj[1]);
            sj[2] = fmaf(wsa.z, v, sj[2]);
            sj[3] = fmaf(wsa.w, v, sj[3]);
            sj[4] = fmaf(wsb.x, v, sj[4]);
            sj[5] = fmaf(wsb.y, v, sj[5]);
            sj[6] = fmaf(wsb.z, v, sj[6]);
            sj[7] = fmaf(wsb.w, v, sj[7]);
            float d = shX[(o & 15) * 128 + pp] - v;
            d2[o >> 4] = fmaf(d, d, d2[o >> 4]);
        }
        // x and rho channels of sigma matvec
#pragma unroll 4
        for (int c = 0; c < 16; c++) {
            float xv = shX[c * 128 + pp];
#pragma unroll
            for (int j = 0; j < 8; j++)
                sj[j] = fmaf(shS[c * 8 + j], xv, sj[j]);
        }
#pragma unroll
        for (int r = 0; r < 8; r++) {
#pragma unroll
            for (int j = 0; j < 8; j++)
                sj[j] = fmaf(shS[(144 + r) * 8 + j], rho[r], sj[j]);
        }

        float gg = shMISC[24];
#pragma unroll
        for (int j = 0; j < 8; j++) {
            float sn = __expf(fmaxf(sj[j], 0.f));
            out[OFF_SIG + (b * 8 + j) * HW + hw0 + pp] = sn;
            float s2 = sn * sn;
            float tt = 6.283185307179586f * s2;
            float t2 = tt * tt, t4 = t2 * t2;
            float dens2 = __expf(-d2[j] / (2.f * s2)) / (t4 * t4);
            gg = fmaf(shMISC[16 + j], pin[j] * dens2, gg);
        }
        out[OFF_G + b * HW + hw0 + pp] = 1.0f / (1.0f + __expf(-gg));
    }
}

extern "C" void kernel_launch(void* const* d_in, const int* in_sizes, int n_in,
                              void* d_out, int out_size) {
    (void)in_sizes;
    (void)n_in;
    (void)out_size;
    const float* x = (const float*)d_in[0];
    const float* pi = (const float*)d_in[1];
    const float* mu = (const float*)d_in[2];
    const float* sigma = (const float*)d_in[3];
    const float* Wpi = (const float*)d_in[4];
    const float* bpi = (const float*)d_in[5];
    const float* Wmu = (const float*)d_in[6];
    const float* bmu = (const float*)d_in[7];
    const float* Wsig = (const float*)d_in[8];
    const float* bsig = (const float*)d_in[9];
    const float* Wg = (const float*)d_in[10];
    const float* bg = (const float*)d_in[11];
    float* out = (float*)d_out;

    prep_B_kernel<<<(128 * KPAD + 255) / 256, 256>>>(Wmu);

    cudaFuncSetAttribute(gmm_block_kernel,
                         cudaFuncAttributeMaxDynamicSharedMemorySize,
                         SMEM_BYTES);
    gmm_block_kernel<<<2048, 256, SMEM_BYTES>>>(x, pi, mu, sigma, Wpi, bpi,
                                                Wmu, bmu, Wsig, bsig, Wg, bg,
                                                out);
}